// round 12
// baseline (speedup 1.0000x reference)
#include <cuda_runtime.h>

#define BB 2
#define NN 1024
#define DN 128
#define DG 128
#define DE 16
#define MID 64
#define OUTD 128
#define IBMAX 7

__device__ __align__(16) float g_values[BB * NN * OUTD];
__device__ __align__(16) float g_skip[BB * NN * OUTD];
__device__ __align__(16) float g_p1[BB * NN * MID];
__device__ __align__(16) float g_base[BB * NN * MID];

typedef unsigned long long u64;

__device__ __forceinline__ u64 pk2(float lo, float hi) {
    u64 r; asm("mov.b64 %0,{%1,%2};" : "=l"(r) : "f"(lo), "f"(hi)); return r;
}
__device__ __forceinline__ void upk2(u64 v, float& lo, float& hi) {
    asm("mov.b64 {%0,%1},%2;" : "=f"(lo), "=f"(hi) : "l"(v));
}
__device__ __forceinline__ u64 fma2(u64 a, u64 b, u64 c) {
    u64 d; asm("fma.rn.f32x2 %0,%1,%2,%3;" : "=l"(d) : "l"(a), "l"(b), "l"(c)); return d;
}
__device__ __forceinline__ u64 add2(u64 a, u64 b) {
    u64 d; asm("add.rn.f32x2 %0,%1,%2;" : "=l"(d) : "l"(a), "l"(b)); return d;
}

// ---------- per-node precompute: smem-staged W, balanced 296-CTA grid ----------
#define NOUT 448          // 128 + 128 + 64 + 64
__global__ void __launch_bounds__(384) k_stageA(
        const float* __restrict__ feat, const float* __restrict__ gfeat,
        const float* __restrict__ Wg, const float* __restrict__ bg,
        const float* __restrict__ Wm, const float* __restrict__ bm,
        const float* __restrict__ Wsk, const float* __restrict__ bsk,
        const float* __restrict__ W1, const float* __restrict__ b1,
        const float* __restrict__ W2, const float* __restrict__ b2,
        const float* __restrict__ be) {
    __shared__ float fs[IBMAX * DN];
    __shared__ float wsm[16 * NOUT];     // one 16-k tile of all four W's
    int cb = blockIdx.x, b = 0;
    if (cb >= 148) { b = 1; cb -= 148; }
    int nb = (cb < 136) ? 7 : 6;
    int node0 = b * NN + ((cb < 136) ? cb * 7 : 952 + (cb - 136) * 6);
    int t = threadIdx.x;
    for (int idx = t; idx < nb * DN / 4; idx += 384)
        ((float4*)fs)[idx] = ((const float4*)(feat + node0 * DN))[idx];

    // output channel assignment
    float bias; float* dst; int ds; int o = t;
    if (o < OUTD)              { bias = bm[o];  dst = g_values + node0 * OUTD + o; ds = OUTD; }
    else if (o < 2 * OUTD)     { int c = o - OUTD;        bias = bsk[c]; dst = g_skip + node0 * OUTD + c; ds = OUTD; }
    else if (o < 2*OUTD + MID) { int c = o - 2 * OUTD;    bias = b1[c];  dst = g_p1 + node0 * MID + c;  ds = MID; }
    else                       { int c = o - 2*OUTD - MID;
                                 float pg = bg[c];
#pragma unroll 4
                                 for (int k = 0; k < DG; k++) pg += gfeat[b * DG + k] * Wg[k * MID + c];
                                 bias = b2[c] + pg + be[c];
                                 dst = g_base + node0 * MID + c; ds = MID; }

    float acc[IBMAX];
#pragma unroll
    for (int nd = 0; nd < IBMAX; nd++) acc[nd] = 0.f;

    for (int kt = 0; kt < 8; kt++) {
        __syncthreads();   // previous tile's readers done (also covers fs on kt=0)
        // stage rows [kt*16, kt*16+16) of Wm|Wsk|W1|W2, f4-coalesced
        for (int idx = t; idx < 16 * (NOUT / 4); idx += 384) {
            int k = idx / (NOUT / 4), seg = idx % (NOUT / 4);
            int kk = kt * 16 + k;
            float4 v;
            if (seg < 32)       v = ((const float4*)(Wm  + kk * OUTD))[seg];
            else if (seg < 64)  v = ((const float4*)(Wsk + kk * OUTD))[seg - 32];
            else if (seg < 80)  v = ((const float4*)(W1  + kk * MID))[seg - 64];
            else                v = ((const float4*)(W2  + kk * MID))[seg - 80];
            ((float4*)wsm)[idx] = v;
        }
        __syncthreads();
#pragma unroll
        for (int kq = 0; kq < 4; kq++) {
            float w0 = wsm[(kq * 4 + 0) * NOUT + o];
            float w1 = wsm[(kq * 4 + 1) * NOUT + o];
            float w2 = wsm[(kq * 4 + 2) * NOUT + o];
            float w3 = wsm[(kq * 4 + 3) * NOUT + o];
#pragma unroll
            for (int nd = 0; nd < IBMAX; nd++) {
                float4 f = *(const float4*)&fs[nd * DN + kt * 16 + kq * 4];
                acc[nd] += f.x * w0 + f.y * w1 + f.z * w2 + f.w * w3;
            }
        }
    }
#pragma unroll
    for (int nd = 0; nd < IBMAX; nd++)
        if (nd < nb) dst[nd * ds] = acc[nd] + bias;
}

// ---------- fused main kernel (frozen round-11 winner) ----------
#define ESS 260
#define ESB (DE * ESS)                   // 4160
#define OFF_LG (2 * ESB)                 // 8320
#define OFF_WE (OFF_LG + IBMAX * NN)     // 15488
#define WS 160
#define WMS 20
#define SMEM_FLOATS (OFF_WE + DE * WS)   // 18048 (72.2 KB)

__device__ __forceinline__ void est4(float* eb, int f4, float4 v) {
    int jl = f4 >> 2, k0 = (f4 & 3) << 2;
    *(u64*)&eb[(k0 + 0) * ESS + jl * 2] = pk2(v.x, v.x);
    *(u64*)&eb[(k0 + 1) * ESS + jl * 2] = pk2(v.y, v.y);
    *(u64*)&eb[(k0 + 2) * ESS + jl * 2] = pk2(v.z, v.z);
    *(u64*)&eb[(k0 + 3) * ESS + jl * 2] = pk2(v.w, v.w);
}

__global__ void __launch_bounds__(256, 2)
k_main(const float* __restrict__ efeat, const float* __restrict__ adj,
       const float* __restrict__ We, const float* __restrict__ Wa,
       float* __restrict__ out) {
    extern __shared__ float sm[];
    float* es  = sm;
    float* lg  = sm + OFF_LG;
    float* wes = sm + OFF_WE;

    int t  = threadIdx.x;
    int bx = blockIdx.x;
    int b = 0, cb = bx;
    if (cb >= 148) { b = 1; cb -= 148; }
    int ib = (cb < 136) ? 7 : 6;
    int i0 = (cb < 136) ? cb * 7 : 952 + (cb - 136) * 6;

    int mg = t & 7;
    int eg = t >> 3;
    int m0 = mg * 8;

    if (t < 128) {
        int k = t >> 3, m = t & 7;
        float4 w0 = *(const float4*)(We + k * MID + m * 8);
        float4 w1 = *(const float4*)(We + k * MID + m * 8 + 4);
        *(float4*)&wes[k * WS + m * WMS]     = w0;
        *(float4*)&wes[k * WS + m * WMS + 4] = w1;
    }

    u64 wa5[4], wa4[4];
#pragma unroll
    for (int q = 0; q < 4; q++) {
        float a = Wa[m0 + 2 * q], c = Wa[m0 + 2 * q + 1];
        wa5[q] = pk2(0.505f * a, 0.505f * c);
        wa4[q] = pk2(0.495f * a, 0.495f * c);
    }

    const float4* ebase = (const float4*)(efeat + (size_t)b * NN * NN * DE);

    float4 pf0, pf1;
    {
        const float4* src = ebase + (size_t)i0 * 4096;
        pf0 = src[t]; pf1 = src[t + 256];
    }

    u64 p1r[16];
    int buf = 0;

    // -------- phase 1: logits --------
    for (int jt = 0; jt < 8; jt++) {
        {
            const float* pp = g_p1 + ((size_t)(b * NN + jt * 128 + eg * 4)) * MID + m0;
#pragma unroll
            for (int e = 0; e < 4; e++) {
                ulonglong2 q0 = *(const ulonglong2*)(pp + e * MID);
                ulonglong2 q1 = *(const ulonglong2*)(pp + e * MID + 4);
                p1r[e*4+0] = q0.x; p1r[e*4+1] = q0.y;
                p1r[e*4+2] = q1.x; p1r[e*4+3] = q1.y;
            }
        }
        for (int i = 0; i < ib; i++) {
            float* eb = es + (buf & 1) * ESB;
            buf++;

            est4(eb, t, pf0);
            est4(eb, t + 256, pf1);

            {
                int ni = i + 1, njt = jt;
                if (ni == ib) { ni = 0; njt = jt + 1; }
                if (njt < 8) {
                    const float4* src = ebase + (size_t)(i0 + ni) * 4096 + njt * 512;
                    pf0 = src[t]; pf1 = src[t + 256];
                }
            }

            int ig = i0 + i;
            u64 b2r[4];
            {
                const float* gb = g_base + (size_t)(b * NN + ig) * MID + m0;
                ulonglong2 q0 = *(const ulonglong2*)gb;
                ulonglong2 q1 = *(const ulonglong2*)(gb + 4);
                b2r[0] = q0.x; b2r[1] = q0.y; b2r[2] = q1.x; b2r[3] = q1.y;
            }

            __syncthreads();

            u64 acc[16];
#pragma unroll
            for (int e = 0; e < 4; e++) {
#pragma unroll
                for (int q = 0; q < 4; q++) acc[e * 4 + q] = add2(p1r[e * 4 + q], b2r[q]);
            }
#pragma unroll
            for (int k = 0; k < DE; k++) {
                ulonglong2 a01 = *(const ulonglong2*)&eb[k * ESS + eg * 8];
                ulonglong2 a23 = *(const ulonglong2*)&eb[k * ESS + eg * 8 + 4];
                ulonglong2 w01 = *(const ulonglong2*)&wes[k * WS + mg * WMS];
                ulonglong2 w23 = *(const ulonglong2*)&wes[k * WS + mg * WMS + 4];
                acc[0]  = fma2(a01.x, w01.x, acc[0]);
                acc[1]  = fma2(a01.x, w01.y, acc[1]);
                acc[2]  = fma2(a01.x, w23.x, acc[2]);
                acc[3]  = fma2(a01.x, w23.y, acc[3]);
                acc[4]  = fma2(a01.y, w01.x, acc[4]);
                acc[5]  = fma2(a01.y, w01.y, acc[5]);
                acc[6]  = fma2(a01.y, w23.x, acc[6]);
                acc[7]  = fma2(a01.y, w23.y, acc[7]);
                acc[8]  = fma2(a23.x, w01.x, acc[8]);
                acc[9]  = fma2(a23.x, w01.y, acc[9]);
                acc[10] = fma2(a23.x, w23.x, acc[10]);
                acc[11] = fma2(a23.x, w23.y, acc[11]);
                acc[12] = fma2(a23.y, w01.x, acc[12]);
                acc[13] = fma2(a23.y, w01.y, acc[13]);
                acc[14] = fma2(a23.y, w23.x, acc[14]);
                acc[15] = fma2(a23.y, w23.y, acc[15]);
            }
            float lres[4];
#pragma unroll
            for (int e = 0; e < 4; e++) {
                u64 p2 = 0ULL;
#pragma unroll
                for (int q = 0; q < 4; q++) {
                    u64 x = acc[e * 4 + q];
                    u64 ax = x & 0x7FFFFFFF7FFFFFFFULL;
                    p2 = fma2(x, wa5[q], p2);
                    p2 = fma2(ax, wa4[q], p2);
                }
                float lo, hi; upk2(p2, lo, hi);
                float part = lo + hi;
                part += __shfl_xor_sync(0xffffffffu, part, 1);
                part += __shfl_xor_sync(0xffffffffu, part, 2);
                part += __shfl_xor_sync(0xffffffffu, part, 4);
                lres[e] = part;
            }
            if (mg == 0)
                *(float4*)&lg[i * NN + jt * 128 + eg * 4] =
                    make_float4(lres[0], lres[1], lres[2], lres[3]);
        }
    }
    __syncthreads();

    // -------- phase 2: masked softmax, warp w -> row w --------
    {
        int w = t >> 5, lane = t & 31;
        if (w < ib) {
            const float* arow = adj + ((size_t)(b * NN + i0 + w)) * NN;
            float mx = -1e30f;
#pragma unroll 4
            for (int s = 0; s < 32; s++) {
                int j = lane + s * 32;
                float x = lg[w * NN + j] + (arow[j] - 1.0f) * 1e9f;
                lg[w * NN + j] = x;
                mx = fmaxf(mx, x);
            }
#pragma unroll
            for (int d = 16; d > 0; d >>= 1) mx = fmaxf(mx, __shfl_xor_sync(~0u, mx, d));
            float sum = 0.f;
#pragma unroll 4
            for (int s = 0; s < 32; s++) {
                int j = lane + s * 32;
                float e = __expf(lg[w * NN + j] - mx);
                lg[w * NN + j] = e;
                sum += e;
            }
#pragma unroll
            for (int d = 16; d > 0; d >>= 1) sum += __shfl_xor_sync(~0u, sum, d);
            float inv = 1.0f / sum;
#pragma unroll 4
            for (int s = 0; s < 32; s++) lg[w * NN + lane + s * 32] *= inv;
        }
    }
    __syncthreads();

    // -------- phase 3: out = relu(coefs @ values + skip), d-quad f32x2 --------
    {
        int jg = t >> 5, dq = t & 31;
        const float* vb = g_values + (size_t)b * NN * OUTD;
        u64 accA[IBMAX], accB[IBMAX];
#pragma unroll
        for (int r = 0; r < IBMAX; r++) { accA[r] = 0ULL; accB[r] = 0ULL; }
        for (int jj = 0; jj < 128; jj++) {
            int j = jg * 128 + jj;
            ulonglong2 v4 = *(const ulonglong2*)&vb[(size_t)j * OUTD + dq * 4];
#pragma unroll
            for (int i = 0; i < IBMAX; i++) {
                float c = lg[i * NN + j];
                u64 cc = pk2(c, c);
                accA[i] = fma2(v4.x, cc, accA[i]);
                accB[i] = fma2(v4.y, cc, accB[i]);
            }
        }
        float* red = sm;
        int base = (jg * 32 + dq) * 30;
#pragma unroll
        for (int i = 0; i < IBMAX; i++) {
            *(u64*)&red[base + i * 4]     = accA[i];
            *(u64*)&red[base + i * 4 + 2] = accB[i];
        }
        __syncthreads();
        for (int idx = t; idx < ib * OUTD; idx += 256) {
            int i = idx >> 7, d = idx & 127;
            int dq2 = d >> 2, dr = d & 3;
            int off = dq2 * 30 + i * 4 + dr;
            float s = 0.f;
#pragma unroll
            for (int g2 = 0; g2 < 8; g2++) s += red[g2 * 960 + off];
            size_t gi = (size_t)(b * NN + i0 + i);
            float v = s + g_skip[gi * OUTD + d];
            out[gi * OUTD + d] = fmaxf(v, 0.f);
        }
    }
}

extern "C" void kernel_launch(void* const* d_in, const int* in_sizes, int n_in,
                              void* d_out, int out_size) {
    const float* feat  = (const float*)d_in[0];
    const float* efeat = (const float*)d_in[1];
    const float* gfeat = (const float*)d_in[2];
    const float* adj   = (const float*)d_in[3];
    const float* Wm    = (const float*)d_in[4];
    const float* bm    = (const float*)d_in[5];
    const float* Wsk   = (const float*)d_in[6];
    const float* bsk   = (const float*)d_in[7];
    const float* W1    = (const float*)d_in[8];
    const float* b1    = (const float*)d_in[9];
    const float* W2    = (const float*)d_in[10];
    const float* b2    = (const float*)d_in[11];
    const float* We    = (const float*)d_in[12];
    const float* be    = (const float*)d_in[13];
    const float* Wg    = (const float*)d_in[14];
    const float* bg    = (const float*)d_in[15];
    const float* Wa    = (const float*)d_in[16];
    float* out = (float*)d_out;

    static int smem_set = 0;
    if (!smem_set) {
        cudaFuncSetAttribute(k_main, cudaFuncAttributeMaxDynamicSharedMemorySize,
                             SMEM_FLOATS * 4);
        smem_set = 1;
    }
    k_stageA<<<BB * 148, 384>>>(feat, gfeat, Wg, bg, Wm, bm, Wsk, bsk, W1, b1, W2, b2, be);
    k_main<<<BB * 148, 256, SMEM_FLOATS * 4>>>(efeat, adj, We, Wa, out);
}

// round 14
// speedup vs baseline: 1.1574x; 1.1574x over previous
#include <cuda_runtime.h>

#define BB 2
#define NN 1024
#define DN 128
#define DG 128
#define DE 16
#define MID 64
#define OUTD 128
#define IBMAX 7

__device__ __align__(16) float g_values[BB * NN * OUTD];
__device__ __align__(16) float g_skip[BB * NN * OUTD];
__device__ __align__(16) float g_p1[BB * NN * MID];
__device__ __align__(16) float g_base[BB * NN * MID];

typedef unsigned long long u64;

__device__ __forceinline__ u64 pk2(float lo, float hi) {
    u64 r; asm("mov.b64 %0,{%1,%2};" : "=l"(r) : "f"(lo), "f"(hi)); return r;
}
__device__ __forceinline__ void upk2(u64 v, float& lo, float& hi) {
    asm("mov.b64 {%0,%1},%2;" : "=f"(lo), "=f"(hi) : "l"(v));
}
__device__ __forceinline__ u64 fma2(u64 a, u64 b, u64 c) {
    u64 d; asm("fma.rn.f32x2 %0,%1,%2,%3;" : "=l"(d) : "l"(a), "l"(b), "l"(c)); return d;
}
__device__ __forceinline__ u64 add2(u64 a, u64 b) {
    u64 d; asm("add.rn.f32x2 %0,%1,%2;" : "=l"(d) : "l"(a), "l"(b)); return d;
}

// ---------- per-node precompute (round-11 version, pg removed) ----------
__global__ void __launch_bounds__(384) k_stageA(
        const float* __restrict__ feat,
        const float* __restrict__ Wm, const float* __restrict__ bm,
        const float* __restrict__ Wsk, const float* __restrict__ bsk,
        const float* __restrict__ W1, const float* __restrict__ b1,
        const float* __restrict__ W2, const float* __restrict__ b2,
        const float* __restrict__ be) {
    __shared__ float fs[IBMAX * DN];
    int cb = blockIdx.x, b = 0;
    if (cb >= 148) { b = 1; cb -= 148; }
    int nb = (cb < 136) ? 7 : 6;
    int node0 = b * NN + ((cb < 136) ? cb * 7 : 952 + (cb - 136) * 6);
    int t = threadIdx.x;
    for (int idx = t; idx < nb * DN / 4; idx += 384)
        ((float4*)fs)[idx] = ((const float4*)(feat + node0 * DN))[idx];
    __syncthreads();
    const float* Wc; float bias; float* dst; int ds, ws;
    int o = t;
    if (o < OUTD)              { Wc = Wm + o;  bias = bm[o];  dst = g_values + node0 * OUTD + o; ds = OUTD; ws = OUTD; }
    else if (o < 2 * OUTD)     { int c = o - OUTD;         Wc = Wsk + c; bias = bsk[c]; dst = g_skip + node0 * OUTD + c; ds = OUTD; ws = OUTD; }
    else if (o < 2*OUTD + MID) { int c = o - 2 * OUTD;     Wc = W1 + c;  bias = b1[c];  dst = g_p1 + node0 * MID + c;  ds = MID; ws = MID; }
    else                       { int c = o - 2*OUTD - MID; Wc = W2 + c;
                                 bias = b2[c] + be[c];     // pg moved to k_main
                                 dst = g_base + node0 * MID + c; ds = MID; ws = MID; }
    float acc[IBMAX];
#pragma unroll
    for (int nd = 0; nd < IBMAX; nd++) acc[nd] = 0.f;
#pragma unroll 4
    for (int kq = 0; kq < DN / 4; kq++) {
        float w0 = Wc[(4*kq+0)*ws], w1 = Wc[(4*kq+1)*ws];
        float w2 = Wc[(4*kq+2)*ws], w3 = Wc[(4*kq+3)*ws];
#pragma unroll
        for (int nd = 0; nd < IBMAX; nd++) {
            float4 f = *(const float4*)&fs[nd * DN + kq * 4];
            acc[nd] += f.x * w0 + f.y * w1 + f.z * w2 + f.w * w3;
        }
    }
#pragma unroll
    for (int nd = 0; nd < IBMAX; nd++)
        if (nd < nb) dst[nd * ds] = acc[nd] + bias;
}

// ---------- fused main kernel (round-11 winner + pg prologue) ----------
#define ESS 260
#define ESB (DE * ESS)                   // 4160
#define OFF_LG (2 * ESB)                 // 8320
#define OFF_WE (OFF_LG + IBMAX * NN)     // 15488
#define WS 160
#define WMS 20
#define OFF_PG (OFF_WE + DE * WS)        // 18048
#define SMEM_FLOATS (OFF_PG + 64)        // 18112 (72.4 KB)

__device__ __forceinline__ void est4(float* eb, int f4, float4 v) {
    int jl = f4 >> 2, k0 = (f4 & 3) << 2;
    *(u64*)&eb[(k0 + 0) * ESS + jl * 2] = pk2(v.x, v.x);
    *(u64*)&eb[(k0 + 1) * ESS + jl * 2] = pk2(v.y, v.y);
    *(u64*)&eb[(k0 + 2) * ESS + jl * 2] = pk2(v.z, v.z);
    *(u64*)&eb[(k0 + 3) * ESS + jl * 2] = pk2(v.w, v.w);
}

__global__ void __launch_bounds__(256, 2)
k_main(const float* __restrict__ efeat, const float* __restrict__ adj,
       const float* __restrict__ We, const float* __restrict__ Wa,
       const float* __restrict__ gfeat, const float* __restrict__ Wg,
       const float* __restrict__ bg,
       float* __restrict__ out) {
    extern __shared__ float sm[];
    float* es  = sm;
    float* lg  = sm + OFF_LG;
    float* wes = sm + OFF_WE;
    float* pgs = sm + OFF_PG;

    int t  = threadIdx.x;
    int bx = blockIdx.x;
    int b = 0, cb = bx;
    if (cb >= 148) { b = 1; cb -= 148; }
    int ib = (cb < 136) ? 7 : 6;
    int i0 = (cb < 136) ? cb * 7 : 952 + (cb - 136) * 6;

    int mg = t & 7;
    int eg = t >> 3;
    int m0 = mg * 8;

    if (t < 128) {
        int k = t >> 3, m = t & 7;
        float4 w0 = *(const float4*)(We + k * MID + m * 8);
        float4 w1 = *(const float4*)(We + k * MID + m * 8 + 4);
        *(float4*)&wes[k * WS + m * WMS]     = w0;
        *(float4*)&wes[k * WS + m * WMS + 4] = w1;
    }

    u64 wa5[4], wa4[4];
#pragma unroll
    for (int q = 0; q < 4; q++) {
        float a = Wa[m0 + 2 * q], c = Wa[m0 + 2 * q + 1];
        wa5[q] = pk2(0.505f * a, 0.505f * c);
        wa4[q] = pk2(0.495f * a, 0.495f * c);
    }

    const float4* ebase = (const float4*)(efeat + (size_t)b * NN * NN * DE);

    float4 pf0, pf1;
    {
        const float4* src = ebase + (size_t)i0 * 4096;
        pf0 = src[t]; pf1 = src[t + 256];
    }

    // ---- pg prologue: pgs[m] = bg[m] + gfeat[b,:] . Wg[:,m] ----
    {
        int mq = t & 63, kp = t >> 6;      // 64 m x 4 k-chunks
        float p = 0.f;
#pragma unroll 8
        for (int k = kp * 32; k < kp * 32 + 32; k++)
            p += gfeat[b * DG + k] * Wg[k * MID + mq];
        lg[t] = p;                          // lg unused until phase 1
        __syncthreads();
        if (t < 64)
            pgs[t] = bg[t] + ((lg[t] + lg[64 + t]) + (lg[128 + t] + lg[192 + t]));
        __syncthreads();
    }
    u64 pg2[4];
#pragma unroll
    for (int q = 0; q < 4; q++) pg2[q] = *(const u64*)&pgs[m0 + 2 * q];

    u64 p1r[16];
    int buf = 0;

    // -------- phase 1: logits --------
    for (int jt = 0; jt < 8; jt++) {
        {
            const float* pp = g_p1 + ((size_t)(b * NN + jt * 128 + eg * 4)) * MID + m0;
#pragma unroll
            for (int e = 0; e < 4; e++) {
                ulonglong2 q0 = *(const ulonglong2*)(pp + e * MID);
                ulonglong2 q1 = *(const ulonglong2*)(pp + e * MID + 4);
                p1r[e*4+0] = add2(q0.x, pg2[0]); p1r[e*4+1] = add2(q0.y, pg2[1]);
                p1r[e*4+2] = add2(q1.x, pg2[2]); p1r[e*4+3] = add2(q1.y, pg2[3]);
            }
        }
        for (int i = 0; i < ib; i++) {
            float* eb = es + (buf & 1) * ESB;
            buf++;

            est4(eb, t, pf0);
            est4(eb, t + 256, pf1);

            {
                int ni = i + 1, njt = jt;
                if (ni == ib) { ni = 0; njt = jt + 1; }
                if (njt < 8) {
                    const float4* src = ebase + (size_t)(i0 + ni) * 4096 + njt * 512;
                    pf0 = src[t]; pf1 = src[t + 256];
                }
            }

            int ig = i0 + i;
            u64 b2r[4];
            {
                const float* gb = g_base + (size_t)(b * NN + ig) * MID + m0;
                ulonglong2 q0 = *(const ulonglong2*)gb;
                ulonglong2 q1 = *(const ulonglong2*)(gb + 4);
                b2r[0] = q0.x; b2r[1] = q0.y; b2r[2] = q1.x; b2r[3] = q1.y;
            }

            __syncthreads();

            u64 acc[16];
#pragma unroll
            for (int e = 0; e < 4; e++) {
#pragma unroll
                for (int q = 0; q < 4; q++) acc[e * 4 + q] = add2(p1r[e * 4 + q], b2r[q]);
            }
#pragma unroll
            for (int k = 0; k < DE; k++) {
                ulonglong2 a01 = *(const ulonglong2*)&eb[k * ESS + eg * 8];
                ulonglong2 a23 = *(const ulonglong2*)&eb[k * ESS + eg * 8 + 4];
                ulonglong2 w01 = *(const ulonglong2*)&wes[k * WS + mg * WMS];
                ulonglong2 w23 = *(const ulonglong2*)&wes[k * WS + mg * WMS + 4];
                acc[0]  = fma2(a01.x, w01.x, acc[0]);
                acc[1]  = fma2(a01.x, w01.y, acc[1]);
                acc[2]  = fma2(a01.x, w23.x, acc[2]);
                acc[3]  = fma2(a01.x, w23.y, acc[3]);
                acc[4]  = fma2(a01.y, w01.x, acc[4]);
                acc[5]  = fma2(a01.y, w01.y, acc[5]);
                acc[6]  = fma2(a01.y, w23.x, acc[6]);
                acc[7]  = fma2(a01.y, w23.y, acc[7]);
                acc[8]  = fma2(a23.x, w01.x, acc[8]);
                acc[9]  = fma2(a23.x, w01.y, acc[9]);
                acc[10] = fma2(a23.x, w23.x, acc[10]);
                acc[11] = fma2(a23.x, w23.y, acc[11]);
                acc[12] = fma2(a23.y, w01.x, acc[12]);
                acc[13] = fma2(a23.y, w01.y, acc[13]);
                acc[14] = fma2(a23.y, w23.x, acc[14]);
                acc[15] = fma2(a23.y, w23.y, acc[15]);
            }
            float lres[4];
#pragma unroll
            for (int e = 0; e < 4; e++) {
                u64 p2 = 0ULL;
#pragma unroll
                for (int q = 0; q < 4; q++) {
                    u64 x = acc[e * 4 + q];
                    u64 ax = x & 0x7FFFFFFF7FFFFFFFULL;
                    p2 = fma2(x, wa5[q], p2);
                    p2 = fma2(ax, wa4[q], p2);
                }
                float lo, hi; upk2(p2, lo, hi);
                float part = lo + hi;
                part += __shfl_xor_sync(0xffffffffu, part, 1);
                part += __shfl_xor_sync(0xffffffffu, part, 2);
                part += __shfl_xor_sync(0xffffffffu, part, 4);
                lres[e] = part;
            }
            if (mg == 0)
                *(float4*)&lg[i * NN + jt * 128 + eg * 4] =
                    make_float4(lres[0], lres[1], lres[2], lres[3]);
        }
    }
    __syncthreads();

    // -------- phase 2: masked softmax, warp w -> row w --------
    {
        int w = t >> 5, lane = t & 31;
        if (w < ib) {
            const float* arow = adj + ((size_t)(b * NN + i0 + w)) * NN;
            float mx = -1e30f;
#pragma unroll 4
            for (int s = 0; s < 32; s++) {
                int j = lane + s * 32;
                float x = lg[w * NN + j] + (arow[j] - 1.0f) * 1e9f;
                lg[w * NN + j] = x;
                mx = fmaxf(mx, x);
            }
#pragma unroll
            for (int d = 16; d > 0; d >>= 1) mx = fmaxf(mx, __shfl_xor_sync(~0u, mx, d));
            float sum = 0.f;
#pragma unroll 4
            for (int s = 0; s < 32; s++) {
                int j = lane + s * 32;
                float e = __expf(lg[w * NN + j] - mx);
                lg[w * NN + j] = e;
                sum += e;
            }
#pragma unroll
            for (int d = 16; d > 0; d >>= 1) sum += __shfl_xor_sync(~0u, sum, d);
            float inv = 1.0f / sum;
#pragma unroll 4
            for (int s = 0; s < 32; s++) lg[w * NN + lane + s * 32] *= inv;
        }
    }
    __syncthreads();

    // -------- phase 3: out = relu(coefs @ values + skip), d-quad f32x2 --------
    {
        int jg = t >> 5, dq = t & 31;
        const float* vb = g_values + (size_t)b * NN * OUTD;
        u64 accA[IBMAX], accB[IBMAX];
#pragma unroll
        for (int r = 0; r < IBMAX; r++) { accA[r] = 0ULL; accB[r] = 0ULL; }
        for (int jj = 0; jj < 128; jj++) {
            int j = jg * 128 + jj;
            ulonglong2 v4 = *(const ulonglong2*)&vb[(size_t)j * OUTD + dq * 4];
#pragma unroll
            for (int i = 0; i < IBMAX; i++) {
                float c = lg[i * NN + j];
                u64 cc = pk2(c, c);
                accA[i] = fma2(v4.x, cc, accA[i]);
                accB[i] = fma2(v4.y, cc, accB[i]);
            }
        }
        float* red = sm;
        int base = (jg * 32 + dq) * 30;
#pragma unroll
        for (int i = 0; i < IBMAX; i++) {
            *(u64*)&red[base + i * 4]     = accA[i];
            *(u64*)&red[base + i * 4 + 2] = accB[i];
        }
        __syncthreads();
        for (int idx = t; idx < ib * OUTD; idx += 256) {
            int i = idx >> 7, d = idx & 127;
            int dq2 = d >> 2, dr = d & 3;
            int off = dq2 * 30 + i * 4 + dr;
            float s = 0.f;
#pragma unroll
            for (int g2 = 0; g2 < 8; g2++) s += red[g2 * 960 + off];
            size_t gi = (size_t)(b * NN + i0 + i);
            float v = s + g_skip[gi * OUTD + d];
            out[gi * OUTD + d] = fmaxf(v, 0.f);
        }
    }
}

extern "C" void kernel_launch(void* const* d_in, const int* in_sizes, int n_in,
                              void* d_out, int out_size) {
    const float* feat  = (const float*)d_in[0];
    const float* efeat = (const float*)d_in[1];
    const float* gfeat = (const float*)d_in[2];
    const float* adj   = (const float*)d_in[3];
    const float* Wm    = (const float*)d_in[4];
    const float* bm    = (const float*)d_in[5];
    const float* Wsk   = (const float*)d_in[6];
    const float* bsk   = (const float*)d_in[7];
    const float* W1    = (const float*)d_in[8];
    const float* b1    = (const float*)d_in[9];
    const float* W2    = (const float*)d_in[10];
    const float* b2    = (const float*)d_in[11];
    const float* We    = (const float*)d_in[12];
    const float* be    = (const float*)d_in[13];
    const float* Wg    = (const float*)d_in[14];
    const float* bg    = (const float*)d_in[15];
    const float* Wa    = (const float*)d_in[16];
    float* out = (float*)d_out;

    static int smem_set = 0;
    if (!smem_set) {
        cudaFuncSetAttribute(k_main, cudaFuncAttributeMaxDynamicSharedMemorySize,
                             SMEM_FLOATS * 4);
        smem_set = 1;
    }
    k_stageA<<<BB * 148, 384>>>(feat, Wm, bm, Wsk, bsk, W1, b1, W2, b2, be);
    k_main<<<BB * 148, 256, SMEM_FLOATS * 4>>>(efeat, adj, We, Wa, gfeat, Wg, bg, out);
}

// round 17
// speedup vs baseline: 1.1679x; 1.0090x over previous
#include <cuda_runtime.h>

#define BB 2
#define NN 1024
#define DN 128
#define DG 128
#define DE 16
#define MID 64
#define OUTD 128
#define IBMAX 7

__device__ __align__(16) float g_values[BB * NN * OUTD];
__device__ __align__(16) float g_skip[BB * NN * OUTD];
__device__ __align__(16) float g_p1[BB * NN * MID];
__device__ __align__(16) float g_base[BB * NN * MID];

typedef unsigned long long u64;

__device__ __forceinline__ u64 pk2(float lo, float hi) {
    u64 r; asm("mov.b64 %0,{%1,%2};" : "=l"(r) : "f"(lo), "f"(hi)); return r;
}
__device__ __forceinline__ void upk2(u64 v, float& lo, float& hi) {
    asm("mov.b64 {%0,%1},%2;" : "=f"(lo), "=f"(hi) : "l"(v));
}
__device__ __forceinline__ u64 fma2(u64 a, u64 b, u64 c) {
    u64 d; asm("fma.rn.f32x2 %0,%1,%2,%3;" : "=l"(d) : "l"(a), "l"(b), "l"(c)); return d;
}
__device__ __forceinline__ u64 add2(u64 a, u64 b) {
    u64 d; asm("add.rn.f32x2 %0,%1,%2;" : "=l"(d) : "l"(a), "l"(b)); return d;
}

// ---------- per-node precompute: fine 592-CTA grid (4/3 nodes per CTA) ----------
__global__ void __launch_bounds__(384) k_stageA(
        const float* __restrict__ feat,
        const float* __restrict__ Wm, const float* __restrict__ bm,
        const float* __restrict__ Wsk, const float* __restrict__ bsk,
        const float* __restrict__ W1, const float* __restrict__ b1,
        const float* __restrict__ W2, const float* __restrict__ b2,
        const float* __restrict__ be) {
    __shared__ float fs[4 * DN];
    int cb = blockIdx.x, b = 0;
    if (cb >= 296) { b = 1; cb -= 296; }
    int nb = (cb < 136) ? 4 : 3;                       // 136*4 + 160*3 = 1024
    int node0 = b * NN + ((cb < 136) ? cb * 4 : 544 + (cb - 136) * 3);
    int t = threadIdx.x;
    for (int idx = t; idx < nb * DN / 4; idx += 384)
        ((float4*)fs)[idx] = ((const float4*)(feat + node0 * DN))[idx];
    __syncthreads();
    const float* Wc; float bias; float* dst; int ds, ws;
    int o = t;
    if (o < OUTD)              { Wc = Wm + o;  bias = bm[o];  dst = g_values + node0 * OUTD + o; ds = OUTD; ws = OUTD; }
    else if (o < 2 * OUTD)     { int c = o - OUTD;         Wc = Wsk + c; bias = bsk[c]; dst = g_skip + node0 * OUTD + c; ds = OUTD; ws = OUTD; }
    else if (o < 2*OUTD + MID) { int c = o - 2 * OUTD;     Wc = W1 + c;  bias = b1[c];  dst = g_p1 + node0 * MID + c;  ds = MID; ws = MID; }
    else                       { int c = o - 2*OUTD - MID; Wc = W2 + c;
                                 bias = b2[c] + be[c];     // pg folded in k_main
                                 dst = g_base + node0 * MID + c; ds = MID; ws = MID; }
    float acc[4];
#pragma unroll
    for (int nd = 0; nd < 4; nd++) acc[nd] = 0.f;
#pragma unroll 4
    for (int kq = 0; kq < DN / 4; kq++) {
        float w0 = Wc[(4*kq+0)*ws], w1 = Wc[(4*kq+1)*ws];
        float w2 = Wc[(4*kq+2)*ws], w3 = Wc[(4*kq+3)*ws];
#pragma unroll
        for (int nd = 0; nd < 4; nd++) {
            float4 f = *(const float4*)&fs[nd * DN + kq * 4];
            acc[nd] += f.x * w0 + f.y * w1 + f.z * w2 + f.w * w3;
        }
    }
#pragma unroll
    for (int nd = 0; nd < 4; nd++)
        if (nd < nb) dst[nd * ds] = acc[nd] + bias;
}

// ---------- fused main kernel (frozen round-14 winner) ----------
#define ESS 260
#define ESB (DE * ESS)                   // 4160
#define OFF_LG (2 * ESB)                 // 8320
#define OFF_WE (OFF_LG + IBMAX * NN)     // 15488
#define WS 160
#define WMS 20
#define OFF_PG (OFF_WE + DE * WS)        // 18048
#define SMEM_FLOATS (OFF_PG + 64)        // 18112 (72.4 KB)

__device__ __forceinline__ void est4(float* eb, int f4, float4 v) {
    int jl = f4 >> 2, k0 = (f4 & 3) << 2;
    *(u64*)&eb[(k0 + 0) * ESS + jl * 2] = pk2(v.x, v.x);
    *(u64*)&eb[(k0 + 1) * ESS + jl * 2] = pk2(v.y, v.y);
    *(u64*)&eb[(k0 + 2) * ESS + jl * 2] = pk2(v.z, v.z);
    *(u64*)&eb[(k0 + 3) * ESS + jl * 2] = pk2(v.w, v.w);
}

__global__ void __launch_bounds__(256, 2)
k_main(const float* __restrict__ efeat, const float* __restrict__ adj,
       const float* __restrict__ We, const float* __restrict__ Wa,
       const float* __restrict__ gfeat, const float* __restrict__ Wg,
       const float* __restrict__ bg,
       float* __restrict__ out) {
    extern __shared__ float sm[];
    float* es  = sm;
    float* lg  = sm + OFF_LG;
    float* wes = sm + OFF_WE;
    float* pgs = sm + OFF_PG;

    int t  = threadIdx.x;
    int bx = blockIdx.x;
    int b = 0, cb = bx;
    if (cb >= 148) { b = 1; cb -= 148; }
    int ib = (cb < 136) ? 7 : 6;
    int i0 = (cb < 136) ? cb * 7 : 952 + (cb - 136) * 6;

    int mg = t & 7;
    int eg = t >> 3;
    int m0 = mg * 8;

    if (t < 128) {
        int k = t >> 3, m = t & 7;
        float4 w0 = *(const float4*)(We + k * MID + m * 8);
        float4 w1 = *(const float4*)(We + k * MID + m * 8 + 4);
        *(float4*)&wes[k * WS + m * WMS]     = w0;
        *(float4*)&wes[k * WS + m * WMS + 4] = w1;
    }

    u64 wa5[4], wa4[4];
#pragma unroll
    for (int q = 0; q < 4; q++) {
        float a = Wa[m0 + 2 * q], c = Wa[m0 + 2 * q + 1];
        wa5[q] = pk2(0.505f * a, 0.505f * c);
        wa4[q] = pk2(0.495f * a, 0.495f * c);
    }

    const float4* ebase = (const float4*)(efeat + (size_t)b * NN * NN * DE);

    float4 pf0, pf1;
    {
        const float4* src = ebase + (size_t)i0 * 4096;
        pf0 = src[t]; pf1 = src[t + 256];
    }

    // ---- pg prologue: pgs[m] = bg[m] + gfeat[b,:] . Wg[:,m] ----
    {
        int mq = t & 63, kp = t >> 6;
        float p = 0.f;
#pragma unroll 8
        for (int k = kp * 32; k < kp * 32 + 32; k++)
            p += gfeat[b * DG + k] * Wg[k * MID + mq];
        lg[t] = p;
        __syncthreads();
        if (t < 64)
            pgs[t] = bg[t] + ((lg[t] + lg[64 + t]) + (lg[128 + t] + lg[192 + t]));
        __syncthreads();
    }
    u64 pg2[4];
#pragma unroll
    for (int q = 0; q < 4; q++) pg2[q] = *(const u64*)&pgs[m0 + 2 * q];

    u64 p1r[16];
    int buf = 0;

    // -------- phase 1: logits --------
    for (int jt = 0; jt < 8; jt++) {
        {
            const float* pp = g_p1 + ((size_t)(b * NN + jt * 128 + eg * 4)) * MID + m0;
#pragma unroll
            for (int e = 0; e < 4; e++) {
                ulonglong2 q0 = *(const ulonglong2*)(pp + e * MID);
                ulonglong2 q1 = *(const ulonglong2*)(pp + e * MID + 4);
                p1r[e*4+0] = add2(q0.x, pg2[0]); p1r[e*4+1] = add2(q0.y, pg2[1]);
                p1r[e*4+2] = add2(q1.x, pg2[2]); p1r[e*4+3] = add2(q1.y, pg2[3]);
            }
        }
        for (int i = 0; i < ib; i++) {
            float* eb = es + (buf & 1) * ESB;
            buf++;

            est4(eb, t, pf0);
            est4(eb, t + 256, pf1);

            {
                int ni = i + 1, njt = jt;
                if (ni == ib) { ni = 0; njt = jt + 1; }
                if (njt < 8) {
                    const float4* src = ebase + (size_t)(i0 + ni) * 4096 + njt * 512;
                    pf0 = src[t]; pf1 = src[t + 256];
                }
            }

            int ig = i0 + i;
            u64 b2r[4];
            {
                const float* gb = g_base + (size_t)(b * NN + ig) * MID + m0;
                ulonglong2 q0 = *(const ulonglong2*)gb;
                ulonglong2 q1 = *(const ulonglong2*)(gb + 4);
                b2r[0] = q0.x; b2r[1] = q0.y; b2r[2] = q1.x; b2r[3] = q1.y;
            }

            __syncthreads();

            u64 acc[16];
#pragma unroll
            for (int e = 0; e < 4; e++) {
#pragma unroll
                for (int q = 0; q < 4; q++) acc[e * 4 + q] = add2(p1r[e * 4 + q], b2r[q]);
            }
#pragma unroll
            for (int k = 0; k < DE; k++) {
                ulonglong2 a01 = *(const ulonglong2*)&eb[k * ESS + eg * 8];
                ulonglong2 a23 = *(const ulonglong2*)&eb[k * ESS + eg * 8 + 4];
                ulonglong2 w01 = *(const ulonglong2*)&wes[k * WS + mg * WMS];
                ulonglong2 w23 = *(const ulonglong2*)&wes[k * WS + mg * WMS + 4];
                acc[0]  = fma2(a01.x, w01.x, acc[0]);
                acc[1]  = fma2(a01.x, w01.y, acc[1]);
                acc[2]  = fma2(a01.x, w23.x, acc[2]);
                acc[3]  = fma2(a01.x, w23.y, acc[3]);
                acc[4]  = fma2(a01.y, w01.x, acc[4]);
                acc[5]  = fma2(a01.y, w01.y, acc[5]);
                acc[6]  = fma2(a01.y, w23.x, acc[6]);
                acc[7]  = fma2(a01.y, w23.y, acc[7]);
                acc[8]  = fma2(a23.x, w01.x, acc[8]);
                acc[9]  = fma2(a23.x, w01.y, acc[9]);
                acc[10] = fma2(a23.x, w23.x, acc[10]);
                acc[11] = fma2(a23.x, w23.y, acc[11]);
                acc[12] = fma2(a23.y, w01.x, acc[12]);
                acc[13] = fma2(a23.y, w01.y, acc[13]);
                acc[14] = fma2(a23.y, w23.x, acc[14]);
                acc[15] = fma2(a23.y, w23.y, acc[15]);
            }
            float lres[4];
#pragma unroll
            for (int e = 0; e < 4; e++) {
                u64 p2 = 0ULL;
#pragma unroll
                for (int q = 0; q < 4; q++) {
                    u64 x = acc[e * 4 + q];
                    u64 ax = x & 0x7FFFFFFF7FFFFFFFULL;
                    p2 = fma2(x, wa5[q], p2);
                    p2 = fma2(ax, wa4[q], p2);
                }
                float lo, hi; upk2(p2, lo, hi);
                float part = lo + hi;
                part += __shfl_xor_sync(0xffffffffu, part, 1);
                part += __shfl_xor_sync(0xffffffffu, part, 2);
                part += __shfl_xor_sync(0xffffffffu, part, 4);
                lres[e] = part;
            }
            if (mg == 0)
                *(float4*)&lg[i * NN + jt * 128 + eg * 4] =
                    make_float4(lres[0], lres[1], lres[2], lres[3]);
        }
    }
    __syncthreads();

    // -------- phase 2: masked softmax, warp w -> row w --------
    {
        int w = t >> 5, lane = t & 31;
        if (w < ib) {
            const float* arow = adj + ((size_t)(b * NN + i0 + w)) * NN;
            float mx = -1e30f;
#pragma unroll 4
            for (int s = 0; s < 32; s++) {
                int j = lane + s * 32;
                float x = lg[w * NN + j] + (arow[j] - 1.0f) * 1e9f;
                lg[w * NN + j] = x;
                mx = fmaxf(mx, x);
            }
#pragma unroll
            for (int d = 16; d > 0; d >>= 1) mx = fmaxf(mx, __shfl_xor_sync(~0u, mx, d));
            float sum = 0.f;
#pragma unroll 4
            for (int s = 0; s < 32; s++) {
                int j = lane + s * 32;
                float e = __expf(lg[w * NN + j] - mx);
                lg[w * NN + j] = e;
                sum += e;
            }
#pragma unroll
            for (int d = 16; d > 0; d >>= 1) sum += __shfl_xor_sync(~0u, sum, d);
            float inv = 1.0f / sum;
#pragma unroll 4
            for (int s = 0; s < 32; s++) lg[w * NN + lane + s * 32] *= inv;
        }
    }
    __syncthreads();

    // -------- phase 3: out = relu(coefs @ values + skip), d-quad f32x2 --------
    {
        int jg = t >> 5, dq = t & 31;
        const float* vb = g_values + (size_t)b * NN * OUTD;
        u64 accA[IBMAX], accB[IBMAX];
#pragma unroll
        for (int r = 0; r < IBMAX; r++) { accA[r] = 0ULL; accB[r] = 0ULL; }
        for (int jj = 0; jj < 128; jj++) {
            int j = jg * 128 + jj;
            ulonglong2 v4 = *(const ulonglong2*)&vb[(size_t)j * OUTD + dq * 4];
#pragma unroll
            for (int i = 0; i < IBMAX; i++) {
                float c = lg[i * NN + j];
                u64 cc = pk2(c, c);
                accA[i] = fma2(v4.x, cc, accA[i]);
                accB[i] = fma2(v4.y, cc, accB[i]);
            }
        }
        float* red = sm;
        int base = (jg * 32 + dq) * 30;
#pragma unroll
        for (int i = 0; i < IBMAX; i++) {
            *(u64*)&red[base + i * 4]     = accA[i];
            *(u64*)&red[base + i * 4 + 2] = accB[i];
        }
        __syncthreads();
        for (int idx = t; idx < ib * OUTD; idx += 256) {
            int i = idx >> 7, d = idx & 127;
            int dq2 = d >> 2, dr = d & 3;
            int off = dq2 * 30 + i * 4 + dr;
            float s = 0.f;
#pragma unroll
            for (int g2 = 0; g2 < 8; g2++) s += red[g2 * 960 + off];
            size_t gi = (size_t)(b * NN + i0 + i);
            float v = s + g_skip[gi * OUTD + d];
            out[gi * OUTD + d] = fmaxf(v, 0.f);
        }
    }
}

extern "C" void kernel_launch(void* const* d_in, const int* in_sizes, int n_in,
                              void* d_out, int out_size) {
    const float* feat  = (const float*)d_in[0];
    const float* efeat = (const float*)d_in[1];
    const float* gfeat = (const float*)d_in[2];
    const float* adj   = (const float*)d_in[3];
    const float* Wm    = (const float*)d_in[4];
    const float* bm    = (const float*)d_in[5];
    const float* Wsk   = (const float*)d_in[6];
    const float* bsk   = (const float*)d_in[7];
    const float* W1    = (const float*)d_in[8];
    const float* b1    = (const float*)d_in[9];
    const float* W2    = (const float*)d_in[10];
    const float* b2    = (const float*)d_in[11];
    const float* We    = (const float*)d_in[12];
    const float* be    = (const float*)d_in[13];
    const float* Wg    = (const float*)d_in[14];
    const float* bg    = (const float*)d_in[15];
    const float* Wa    = (const float*)d_in[16];
    float* out = (float*)d_out;

    static int smem_set = 0;
    if (!smem_set) {
        cudaFuncSetAttribute(k_main, cudaFuncAttributeMaxDynamicSharedMemorySize,
                             SMEM_FLOATS * 4);
        smem_set = 1;
    }
    k_stageA<<<2 * 296, 384>>>(feat, Wm, bm, Wsk, bsk, W1, b1, W2, b2, be);
    k_main<<<BB * 148, 256, SMEM_FLOATS * 4>>>(efeat, adj, We, Wa, gfeat, Wg, bg, out);
}